// round 14
// baseline (speedup 1.0000x reference)
#include <cuda_runtime.h>
#include <cuda_bf16.h>
#include <cstdint>
#include <cstddef>

// Dims:
// x  : 131072 floats                  = (2048 ij, 64 m)
// Ci : 4194304 floats (512,4,512,4)   = (2048 ij, 2048 kl), values exactly {0,1}
// Wi : 33554432 floats (512,4,4,64,64)-> flat b*16384 + k*4096 + l*64 + m, b=i*4+j
// y  : 131072 floats (512,4,64)       -> b*64 + l
//
// xr[kl, m] = sum_ij Ci[ij,kl] * x[ij,m]
// y[b, l]   = sum_{k,m} Wi[b,k,l,m] * xr[(b>>2)*256 + k*64 + m]

#define N_KL   2048
#define N_M    64
#define XR_N   131072
#define NCHUNK 16      // ij splits (128 ij each)
#define NKLT   32      // kl tiles (64 kl each)
#define IJB    128

__device__ float g_part[NCHUNK * XR_N];   // 8 MB partials (L2-resident)
__device__ float g_xr[XR_N];              // 512 KB reduced
__device__ int   g_cnt[NKLT];             // monotonic per-tile counters
                                          // ((old+1)&15)==0 -> last of this launch;
                                          // no reset needed across graph replays.

// Route dynamic smem: 3 tiles of 128 rows x 128 bytes, SW128-swizzled
#define SM_A   0        // Ci bf16 [128 ij][64 kl]
#define SM_XH  16384    // x hi bf16 [128 ij][64 m]
#define SM_XL  32768    // x lo bf16 [128 ij][64 m]
#define SMEM_ROUTE 49152

__device__ __forceinline__ uint32_t swz(uint32_t off) {
    return off ^ ((off >> 3) & 0x70);
}

__device__ __forceinline__ void ldsm4t(uint32_t& r0, uint32_t& r1,
                                       uint32_t& r2, uint32_t& r3, uint32_t addr) {
    asm volatile("ldmatrix.sync.aligned.m8n8.x4.trans.shared.b16 {%0,%1,%2,%3}, [%4];"
                 : "=r"(r0), "=r"(r1), "=r"(r2), "=r"(r3) : "r"(addr));
}

__device__ __forceinline__ void mma16816(float* c, uint32_t a0, uint32_t a1,
                                         uint32_t a2, uint32_t a3,
                                         uint32_t b0, uint32_t b1) {
    asm volatile("mma.sync.aligned.m16n8k16.row.col.f32.bf16.bf16.f32 "
                 "{%0,%1,%2,%3}, {%4,%5,%6,%7}, {%8,%9}, {%0,%1,%2,%3};"
                 : "+f"(c[0]), "+f"(c[1]), "+f"(c[2]), "+f"(c[3])
                 : "r"(a0), "r"(a1), "r"(a2), "r"(a3), "r"(b0), "r"(b1));
}

// ---------------------------------------------------------------------------
// Kernel 1: routing via bf16 tensor cores (fp32 accuracy by hi/lo x split),
// with last-block fold per kl-tile -> writes g_xr directly (no reduce kernel,
// no redundant per-consumer folds).
// grid = 512: klt = bx&31 (x chunk shared in L2), chunk = bx>>5.
// PDL: triggers downstream (transform) right after staging so the transform's
// Wi prefetch streams DRAM while this mainloop + fold run.
// ---------------------------------------------------------------------------
__global__ void __launch_bounds__(256) route_kernel(const float* __restrict__ Ci,
                                                    const float* __restrict__ x)
{
    extern __shared__ unsigned char sm[];
    const uint32_t sbase = (uint32_t)__cvta_generic_to_shared(sm);

    const int bx    = blockIdx.x;
    const int klt   = bx & 31;
    const int chunk = bx >> 5;
    const int t     = threadIdx.x;
    const int kl0   = klt * 64;
    const int ij0   = chunk * IJB;

    // --- Stage Ci tile: 128 ij x 64 kl. Front-batch 8 LDG.128; bf16 via PRMT
    //     (Ci values are exactly {0,1}: truncating fp32 to its top half is exact).
    {
        float4 va[8];
        #pragma unroll
        for (int p = 0; p < 8; p++) {
            int f = p * 256 + t;
            int r = f >> 4, c4 = f & 15;
            va[p] = *reinterpret_cast<const float4*>(
                Ci + (size_t)(ij0 + r) * N_KL + kl0 + c4 * 4);
        }
        #pragma unroll
        for (int p = 0; p < 8; p++) {
            int f = p * 256 + t;
            int r = f >> 4, c4 = f & 15;
            unsigned u0 = __byte_perm(__float_as_uint(va[p].x),
                                      __float_as_uint(va[p].y), 0x7632);
            unsigned u1 = __byte_perm(__float_as_uint(va[p].z),
                                      __float_as_uint(va[p].w), 0x7632);
            uint32_t off = swz((uint32_t)(r * 128 + c4 * 8));
            *reinterpret_cast<uint2*>(sm + SM_A + off) = make_uint2(u0, u1);
        }
    }
    // --- Stage x tile: 128 ij x 64 m. Front-batch 8 LDG.128, hi/lo split.
    {
        float4 vx[8];
        #pragma unroll
        for (int p = 0; p < 8; p++) {
            int f = p * 256 + t;
            int r = f >> 4, m4 = f & 15;
            vx[p] = *reinterpret_cast<const float4*>(
                x + (size_t)(ij0 + r) * N_M + m4 * 4);
        }
        #pragma unroll
        for (int p = 0; p < 8; p++) {
            int f = p * 256 + t;
            int r = f >> 4, m4 = f & 15;
            float4 v = vx[p];
            __nv_bfloat162 h01 = __floats2bfloat162_rn(v.x, v.y);
            __nv_bfloat162 h23 = __floats2bfloat162_rn(v.z, v.w);
            float2 f01 = __bfloat1622float2(h01);
            float2 f23 = __bfloat1622float2(h23);
            __nv_bfloat162 l01 = __floats2bfloat162_rn(v.x - f01.x, v.y - f01.y);
            __nv_bfloat162 l23 = __floats2bfloat162_rn(v.z - f23.x, v.w - f23.y);
            uint32_t off = swz((uint32_t)(r * 128 + m4 * 8));
            *reinterpret_cast<uint2*>(sm + SM_XH + off) =
                make_uint2(*reinterpret_cast<unsigned*>(&h01),
                           *reinterpret_cast<unsigned*>(&h23));
            *reinterpret_cast<uint2*>(sm + SM_XL + off) =
                make_uint2(*reinterpret_cast<unsigned*>(&l01),
                           *reinterpret_cast<unsigned*>(&l23));
        }
    }
    __syncthreads();

#if __CUDA_ARCH__ >= 900
    // Staging done: let the transform kernel start launching + prefetching Wi.
    cudaTriggerProgrammaticLaunchCompletion();
#endif

    const int w     = t >> 5;
    const int lane  = t & 31;
    const int klgrp = w >> 1;     // 0..3 -> 16-kl sub-block
    const int mgrp  = w & 1;      // 0..1 -> m base 0/32

    const int aRow  = (lane & 7) + ((lane >> 4) & 1) * 8;
    const int aColB = klgrp * 32 + ((lane >> 3) & 1) * 16;
    const int bRow  = (lane & 7) + ((lane >> 3) & 1) * 8;
    const int bCol0 = mgrp * 64 + ((lane >> 4) & 1) * 16;
    const int bCol1 = bCol0 + 32;

    float c[4][4];
    #pragma unroll
    for (int nt = 0; nt < 4; nt++)
        #pragma unroll
        for (int e = 0; e < 4; e++) c[nt][e] = 0.f;

    #pragma unroll
    for (int s = 0; s < 8; s++) {
        const uint32_t rowA = (uint32_t)((s * 16 + aRow) * 128 + aColB);
        const uint32_t rowB = (uint32_t)((s * 16 + bRow) * 128);

        uint32_t a0, a1, a2, a3;
        ldsm4t(a0, a1, a2, a3, sbase + SM_A + swz(rowA));

        uint32_t h0, h1, h2, h3, h4, h5, h6, h7;
        ldsm4t(h0, h1, h2, h3, sbase + SM_XH + swz(rowB + bCol0));
        ldsm4t(h4, h5, h6, h7, sbase + SM_XH + swz(rowB + bCol1));
        uint32_t l0, l1, l2, l3, l4, l5, l6, l7;
        ldsm4t(l0, l1, l2, l3, sbase + SM_XL + swz(rowB + bCol0));
        ldsm4t(l4, l5, l6, l7, sbase + SM_XL + swz(rowB + bCol1));

        mma16816(c[0], a0, a1, a2, a3, h0, h1);
        mma16816(c[1], a0, a1, a2, a3, h2, h3);
        mma16816(c[2], a0, a1, a2, a3, h4, h5);
        mma16816(c[3], a0, a1, a2, a3, h6, h7);
        mma16816(c[0], a0, a1, a2, a3, l0, l1);
        mma16816(c[1], a0, a1, a2, a3, l2, l3);
        mma16816(c[2], a0, a1, a2, a3, l4, l5);
        mma16816(c[3], a0, a1, a2, a3, l6, l7);
    }

    // Epilogue: m16n8 frag -> rows {g, g+8}, cols {2tt, 2tt+1}
    const int g  = lane >> 2;
    const int tt = lane & 3;
    float* dst = g_part + (size_t)chunk * XR_N;
    const int klA = kl0 + klgrp * 16 + g;
    #pragma unroll
    for (int nt = 0; nt < 4; nt++) {
        const int m = mgrp * 32 + nt * 8 + tt * 2;
        *reinterpret_cast<float2*>(&dst[(size_t)klA * N_M + m])       = make_float2(c[nt][0], c[nt][1]);
        *reinterpret_cast<float2*>(&dst[(size_t)(klA + 8) * N_M + m]) = make_float2(c[nt][2], c[nt][3]);
    }

    // --- Last-block fold for this kl-tile: 16 partial slices -> g_xr ---
    __threadfence();          // release our g_part writes (all threads)
    __syncthreads();
    __shared__ int s_last;
    if (t == 0) {
        int old = atomicAdd(&g_cnt[klt], 1);
        s_last = (((old + 1) & (NCHUNK - 1)) == 0);
    }
    __syncthreads();
    if (s_last) {
        __threadfence();      // acquire side of fence-fence sync
        const float4* p4 = reinterpret_cast<const float4*>(g_part);
        float4* xr4 = reinterpret_cast<float4*>(g_xr);
        const int base = kl0 * 16;   // float4 index of this tile's slice
        float4 acc[4];
        #pragma unroll
        for (int e = 0; e < 4; e++) acc[e] = make_float4(0.f, 0.f, 0.f, 0.f);
        #pragma unroll 4
        for (int gch = 0; gch < NCHUNK; gch++) {
            #pragma unroll
            for (int e = 0; e < 4; e++) {
                float4 v = p4[(size_t)gch * (XR_N / 4) + base + t + e * 256];
                acc[e].x += v.x; acc[e].y += v.y;
                acc[e].z += v.z; acc[e].w += v.w;
            }
        }
        #pragma unroll
        for (int e = 0; e < 4; e++)
            xr4[base + t + e * 256] = acc[e];
    }
}

// ---------------------------------------------------------------------------
// Kernel 2: per-capsule transform. grid = 4096. PDL secondary: front-batch
// the block's ENTIRE Wi working set (8 float4/thread, independent of route),
// then grid-dependency sync, then read g_xr (L2-hot) and compute.
// ---------------------------------------------------------------------------
__global__ void __launch_bounds__(256) transform_kernel(const float* __restrict__ Wi,
                                                        float* __restrict__ y)
{
    __shared__ float sxr[256];
    __shared__ float part[32 * 33];

    const int bx   = blockIdx.x;
    const int b    = bx >> 1;
    const int half = bx & 1;
    const int i    = b >> 2;
    const int t    = threadIdx.x;
    const int w    = t >> 5;
    const int L    = t & 31;
    const int ka   = L >> 4;
    const int mi   = L & 15;

    const float4* W4 = reinterpret_cast<const float4*>(Wi + (size_t)b * 16384);
    const int l_base = half * 32 + w * 4;

    // Wi prefetch — independent of route's output, overlaps route via PDL
    float4 wv[4][2];
    #pragma unroll
    for (int qq = 0; qq < 4; qq++) {
        const int l = l_base + qq;
        wv[qq][0] = __ldcs(&W4[ka * 1024 + l * 16 + mi]);
        wv[qq][1] = __ldcs(&W4[(ka + 2) * 1024 + l * 16 + mi]);
    }

#if __CUDA_ARCH__ >= 900
    cudaGridDependencySynchronize();   // wait for route (incl. folds into g_xr)
#endif

    sxr[t] = g_xr[i * 256 + t];
    __syncthreads();

    const float4* sxr4 = reinterpret_cast<const float4*>(sxr);
    const float4 xv0 = sxr4[ka * 16 + mi];
    const float4 xv1 = sxr4[(ka + 2) * 16 + mi];

    #pragma unroll
    for (int qq = 0; qq < 4; qq++) {
        float4 a = wv[qq][0];
        float4 cc = wv[qq][1];
        float acc;
        acc = a.x * xv0.x;
        acc = fmaf(a.y, xv0.y, acc);
        acc = fmaf(a.z, xv0.z, acc);
        acc = fmaf(a.w, xv0.w, acc);
        acc = fmaf(cc.x, xv1.x, acc);
        acc = fmaf(cc.y, xv1.y, acc);
        acc = fmaf(cc.z, xv1.z, acc);
        acc = fmaf(cc.w, xv1.w, acc);
        part[(w * 4 + qq) * 33 + L] = acc;
    }
    __syncthreads();

    if (t < 32) {
        float s = 0.f;
        #pragma unroll
        for (int j = 0; j < 32; j++)
            s += part[t * 33 + j];
        y[b * 64 + half * 32 + t] = s;
    }
}

// ---------------------------------------------------------------------------
extern "C" void kernel_launch(void* const* d_in, const int* in_sizes, int n_in,
                              void* d_out, int out_size)
{
    const float* x  = nullptr;
    const float* Ci = nullptr;
    const float* Wi = nullptr;
    for (int i = 0; i < n_in; i++) {
        if (in_sizes[i] == 131072)        x  = (const float*)d_in[i];
        else if (in_sizes[i] == 4194304)  Ci = (const float*)d_in[i];
        else if (in_sizes[i] == 33554432) Wi = (const float*)d_in[i];
    }
    float* y = (float*)d_out;

    cudaFuncSetAttribute(route_kernel,
                         cudaFuncAttributeMaxDynamicSharedMemorySize,
                         SMEM_ROUTE);

    route_kernel<<<NKLT * NCHUNK, 256, SMEM_ROUTE>>>(Ci, x);

    // Transform as PDL secondary: launches (and prefetches Wi) while route runs.
    cudaLaunchConfig_t cfg = {};
    cfg.gridDim  = dim3(4096, 1, 1);
    cfg.blockDim = dim3(256, 1, 1);
    cfg.dynamicSmemBytes = 0;
    cfg.stream = 0;
    cudaLaunchAttribute at[1];
    at[0].id = cudaLaunchAttributeProgrammaticStreamSerialization;
    at[0].val.programmaticStreamSerializationAllowed = 1;
    cfg.attrs = at;
    cfg.numAttrs = 1;
    cudaLaunchKernelEx(&cfg, transform_kernel, Wi, y);
}

// round 17
// speedup vs baseline: 1.2357x; 1.2357x over previous
#include <cuda_runtime.h>
#include <cuda_bf16.h>
#include <cstdint>
#include <cstddef>

// Dims:
// x  : 131072 floats                  = (2048 ij, 64 m)
// Ci : 4194304 floats (512,4,512,4)   = (2048 ij, 2048 kl), values exactly {0,1}
// Wi : 33554432 floats (512,4,4,64,64)-> flat b*16384 + k*4096 + l*64 + m, b=i*4+j
// y  : 131072 floats (512,4,64)       -> b*64 + l
//
// xr[kl, m] = sum_ij Ci[ij,kl] * x[ij,m]
// y[b, l]   = sum_{k,m} Wi[b,k,l,m] * xr[(b>>2)*256 + k*64 + m]

#define N_KL   2048
#define N_M    64
#define XR_N   131072
#define NCHUNK 16      // ij splits (128 ij each)
#define NKLT   32      // kl tiles (64 kl each)
#define IJB    128

__device__ float g_part[NCHUNK * XR_N];   // 8 MB partials (L2-resident)
__device__ float g_xr[XR_N];              // 512 KB reduced

// Route dynamic smem: 3 tiles of 128 rows x 128 bytes, SW128-swizzled
#define SM_A   0        // Ci bf16 [128 ij][64 kl]
#define SM_XH  16384    // x hi bf16 [128 ij][64 m]
#define SM_XL  32768    // x lo bf16 [128 ij][64 m]
#define SMEM_ROUTE 49152

__device__ __forceinline__ uint32_t swz(uint32_t off) {
    return off ^ ((off >> 3) & 0x70);
}

__device__ __forceinline__ void ldsm4t(uint32_t& r0, uint32_t& r1,
                                       uint32_t& r2, uint32_t& r3, uint32_t addr) {
    asm volatile("ldmatrix.sync.aligned.m8n8.x4.trans.shared.b16 {%0,%1,%2,%3}, [%4];"
                 : "=r"(r0), "=r"(r1), "=r"(r2), "=r"(r3) : "r"(addr));
}

__device__ __forceinline__ void mma16816(float* c, uint32_t a0, uint32_t a1,
                                         uint32_t a2, uint32_t a3,
                                         uint32_t b0, uint32_t b1) {
    asm volatile("mma.sync.aligned.m16n8k16.row.col.f32.bf16.bf16.f32 "
                 "{%0,%1,%2,%3}, {%4,%5,%6,%7}, {%8,%9}, {%0,%1,%2,%3};"
                 : "+f"(c[0]), "+f"(c[1]), "+f"(c[2]), "+f"(c[3])
                 : "r"(a0), "r"(a1), "r"(a2), "r"(a3), "r"(b0), "r"(b1));
}

// ---------------------------------------------------------------------------
// Kernel 1: routing via bf16 tensor cores (fp32 accuracy by hi/lo x split).
// grid = 512: klt = bx&31 (x chunk shared in L2), chunk = bx>>5.
// No fold, no fences (R12-proven 11.7us shape). PDL: triggers downstream
// right after staging so reduce+transform launch while the mainloop runs.
// ---------------------------------------------------------------------------
__global__ void __launch_bounds__(256) route_kernel(const float* __restrict__ Ci,
                                                    const float* __restrict__ x)
{
    extern __shared__ unsigned char sm[];
    const uint32_t sbase = (uint32_t)__cvta_generic_to_shared(sm);

    const int bx    = blockIdx.x;
    const int klt   = bx & 31;
    const int chunk = bx >> 5;
    const int t     = threadIdx.x;
    const int kl0   = klt * 64;
    const int ij0   = chunk * IJB;

    // --- Stage Ci tile: 128 ij x 64 kl. Front-batch 8 LDG.128; bf16 via PRMT
    //     (Ci values are exactly {0,1}: fp32 top half is the exact bf16).
    {
        float4 va[8];
        #pragma unroll
        for (int p = 0; p < 8; p++) {
            int f = p * 256 + t;
            int r = f >> 4, c4 = f & 15;
            va[p] = *reinterpret_cast<const float4*>(
                Ci + (size_t)(ij0 + r) * N_KL + kl0 + c4 * 4);
        }
        #pragma unroll
        for (int p = 0; p < 8; p++) {
            int f = p * 256 + t;
            int r = f >> 4, c4 = f & 15;
            unsigned u0 = __byte_perm(__float_as_uint(va[p].x),
                                      __float_as_uint(va[p].y), 0x7632);
            unsigned u1 = __byte_perm(__float_as_uint(va[p].z),
                                      __float_as_uint(va[p].w), 0x7632);
            uint32_t off = swz((uint32_t)(r * 128 + c4 * 8));
            *reinterpret_cast<uint2*>(sm + SM_A + off) = make_uint2(u0, u1);
        }
    }
    // --- Stage x tile: 128 ij x 64 m. Front-batch 8 LDG.128, hi/lo split.
    {
        float4 vx[8];
        #pragma unroll
        for (int p = 0; p < 8; p++) {
            int f = p * 256 + t;
            int r = f >> 4, m4 = f & 15;
            vx[p] = *reinterpret_cast<const float4*>(
                x + (size_t)(ij0 + r) * N_M + m4 * 4);
        }
        #pragma unroll
        for (int p = 0; p < 8; p++) {
            int f = p * 256 + t;
            int r = f >> 4, m4 = f & 15;
            float4 v = vx[p];
            __nv_bfloat162 h01 = __floats2bfloat162_rn(v.x, v.y);
            __nv_bfloat162 h23 = __floats2bfloat162_rn(v.z, v.w);
            float2 f01 = __bfloat1622float2(h01);
            float2 f23 = __bfloat1622float2(h23);
            __nv_bfloat162 l01 = __floats2bfloat162_rn(v.x - f01.x, v.y - f01.y);
            __nv_bfloat162 l23 = __floats2bfloat162_rn(v.z - f23.x, v.w - f23.y);
            uint32_t off = swz((uint32_t)(r * 128 + m4 * 8));
            *reinterpret_cast<uint2*>(sm + SM_XH + off) =
                make_uint2(*reinterpret_cast<unsigned*>(&h01),
                           *reinterpret_cast<unsigned*>(&h23));
            *reinterpret_cast<uint2*>(sm + SM_XL + off) =
                make_uint2(*reinterpret_cast<unsigned*>(&l01),
                           *reinterpret_cast<unsigned*>(&l23));
        }
    }
    __syncthreads();

#if __CUDA_ARCH__ >= 900
    // Staging done: allow the dependent launches to begin (Wi prefetch overlap).
    cudaTriggerProgrammaticLaunchCompletion();
#endif

    const int w     = t >> 5;
    const int lane  = t & 31;
    const int klgrp = w >> 1;     // 0..3 -> 16-kl sub-block
    const int mgrp  = w & 1;      // 0..1 -> m base 0/32

    const int aRow  = (lane & 7) + ((lane >> 4) & 1) * 8;
    const int aColB = klgrp * 32 + ((lane >> 3) & 1) * 16;
    const int bRow  = (lane & 7) + ((lane >> 3) & 1) * 8;
    const int bCol0 = mgrp * 64 + ((lane >> 4) & 1) * 16;
    const int bCol1 = bCol0 + 32;

    float c[4][4];
    #pragma unroll
    for (int nt = 0; nt < 4; nt++)
        #pragma unroll
        for (int e = 0; e < 4; e++) c[nt][e] = 0.f;

    #pragma unroll
    for (int s = 0; s < 8; s++) {
        const uint32_t rowA = (uint32_t)((s * 16 + aRow) * 128 + aColB);
        const uint32_t rowB = (uint32_t)((s * 16 + bRow) * 128);

        uint32_t a0, a1, a2, a3;
        ldsm4t(a0, a1, a2, a3, sbase + SM_A + swz(rowA));

        uint32_t h0, h1, h2, h3, h4, h5, h6, h7;
        ldsm4t(h0, h1, h2, h3, sbase + SM_XH + swz(rowB + bCol0));
        ldsm4t(h4, h5, h6, h7, sbase + SM_XH + swz(rowB + bCol1));
        uint32_t l0, l1, l2, l3, l4, l5, l6, l7;
        ldsm4t(l0, l1, l2, l3, sbase + SM_XL + swz(rowB + bCol0));
        ldsm4t(l4, l5, l6, l7, sbase + SM_XL + swz(rowB + bCol1));

        mma16816(c[0], a0, a1, a2, a3, h0, h1);
        mma16816(c[1], a0, a1, a2, a3, h2, h3);
        mma16816(c[2], a0, a1, a2, a3, h4, h5);
        mma16816(c[3], a0, a1, a2, a3, h6, h7);
        mma16816(c[0], a0, a1, a2, a3, l0, l1);
        mma16816(c[1], a0, a1, a2, a3, l2, l3);
        mma16816(c[2], a0, a1, a2, a3, l4, l5);
        mma16816(c[3], a0, a1, a2, a3, l6, l7);
    }

    // Epilogue: m16n8 frag -> rows {g, g+8}, cols {2tt, 2tt+1}
    const int g  = lane >> 2;
    const int tt = lane & 3;
    float* dst = g_part + (size_t)chunk * XR_N;
    const int klA = kl0 + klgrp * 16 + g;
    #pragma unroll
    for (int nt = 0; nt < 4; nt++) {
        const int m = mgrp * 32 + nt * 8 + tt * 2;
        *reinterpret_cast<float2*>(&dst[(size_t)klA * N_M + m])       = make_float2(c[nt][0], c[nt][1]);
        *reinterpret_cast<float2*>(&dst[(size_t)(klA + 8) * N_M + m]) = make_float2(c[nt][2], c[nt][3]);
    }
}

// ---------------------------------------------------------------------------
// Kernel 2: fold 16 partials -> xr (~8.5 MB L2 traffic). PDL middle link:
// trigger PLC at entry (so transform launches + prefetches during route),
// THEN gridsync (waits for route), then fold.
// ---------------------------------------------------------------------------
__global__ void __launch_bounds__(256) reduce_kernel()
{
#if __CUDA_ARCH__ >= 900
    cudaTriggerProgrammaticLaunchCompletion();
    cudaGridDependencySynchronize();   // g_part complete
#endif
    int t = blockIdx.x * 256 + threadIdx.x;
    float s0 = 0.f, s1 = 0.f;
    #pragma unroll
    for (int g = 0; g < NCHUNK; g += 2) {
        s0 += g_part[(size_t)g * XR_N + t];
        s1 += g_part[(size_t)(g + 1) * XR_N + t];
    }
    g_xr[t] = s0 + s1;
}

// ---------------------------------------------------------------------------
// Kernel 3: per-capsule transform. grid = 4096. PDL secondary: front-batch
// the block's entire Wi working set (8 float4/thread, independent of route),
// then grid-dependency sync (waits for reduce), then compute.
// ---------------------------------------------------------------------------
__global__ void __launch_bounds__(256) transform_kernel(const float* __restrict__ Wi,
                                                        float* __restrict__ y)
{
    __shared__ float sxr[256];
    __shared__ float part[32 * 33];

    const int bx   = blockIdx.x;
    const int b    = bx >> 1;
    const int half = bx & 1;
    const int i    = b >> 2;
    const int t    = threadIdx.x;
    const int w    = t >> 5;
    const int L    = t & 31;
    const int ka   = L >> 4;
    const int mi   = L & 15;

    const float4* W4 = reinterpret_cast<const float4*>(Wi + (size_t)b * 16384);
    const int l_base = half * 32 + w * 4;

    // Wi prefetch — independent of route/reduce output, overlaps them via PDL
    float4 wv[4][2];
    #pragma unroll
    for (int qq = 0; qq < 4; qq++) {
        const int l = l_base + qq;
        wv[qq][0] = __ldcs(&W4[ka * 1024 + l * 16 + mi]);
        wv[qq][1] = __ldcs(&W4[(ka + 2) * 1024 + l * 16 + mi]);
    }

#if __CUDA_ARCH__ >= 900
    cudaGridDependencySynchronize();   // wait for reduce (g_xr ready)
#endif

    sxr[t] = g_xr[i * 256 + t];
    __syncthreads();

    const float4* sxr4 = reinterpret_cast<const float4*>(sxr);
    const float4 xv0 = sxr4[ka * 16 + mi];
    const float4 xv1 = sxr4[(ka + 2) * 16 + mi];

    #pragma unroll
    for (int qq = 0; qq < 4; qq++) {
        float4 a = wv[qq][0];
        float4 cc = wv[qq][1];
        float acc;
        acc = a.x * xv0.x;
        acc = fmaf(a.y, xv0.y, acc);
        acc = fmaf(a.z, xv0.z, acc);
        acc = fmaf(a.w, xv0.w, acc);
        acc = fmaf(cc.x, xv1.x, acc);
        acc = fmaf(cc.y, xv1.y, acc);
        acc = fmaf(cc.z, xv1.z, acc);
        acc = fmaf(cc.w, xv1.w, acc);
        part[(w * 4 + qq) * 33 + L] = acc;
    }
    __syncthreads();

    if (t < 32) {
        float s = 0.f;
        #pragma unroll
        for (int j = 0; j < 32; j++)
            s += part[t * 33 + j];
        y[b * 64 + half * 32 + t] = s;
    }
}

// ---------------------------------------------------------------------------
extern "C" void kernel_launch(void* const* d_in, const int* in_sizes, int n_in,
                              void* d_out, int out_size)
{
    const float* x  = nullptr;
    const float* Ci = nullptr;
    const float* Wi = nullptr;
    for (int i = 0; i < n_in; i++) {
        if (in_sizes[i] == 131072)        x  = (const float*)d_in[i];
        else if (in_sizes[i] == 4194304)  Ci = (const float*)d_in[i];
        else if (in_sizes[i] == 33554432) Wi = (const float*)d_in[i];
    }
    float* y = (float*)d_out;

    cudaFuncSetAttribute(route_kernel,
                         cudaFuncAttributeMaxDynamicSharedMemorySize,
                         SMEM_ROUTE);

    route_kernel<<<NKLT * NCHUNK, 256, SMEM_ROUTE>>>(Ci, x);

    cudaLaunchAttribute at[1];
    at[0].id = cudaLaunchAttributeProgrammaticStreamSerialization;
    at[0].val.programmaticStreamSerializationAllowed = 1;

    // Reduce as PDL secondary of route (triggers PLC at entry, so transform
    // launches while route is still in its mainloop).
    cudaLaunchConfig_t cfgR = {};
    cfgR.gridDim  = dim3(XR_N / 256, 1, 1);
    cfgR.blockDim = dim3(256, 1, 1);
    cfgR.dynamicSmemBytes = 0;
    cfgR.stream = 0;
    cfgR.attrs = at;
    cfgR.numAttrs = 1;
    cudaLaunchKernelEx(&cfgR, reduce_kernel);

    // Transform as PDL secondary of reduce: prefetches Wi during route+reduce.
    cudaLaunchConfig_t cfgT = {};
    cfgT.gridDim  = dim3(4096, 1, 1);
    cfgT.blockDim = dim3(256, 1, 1);
    cfgT.dynamicSmemBytes = 0;
    cfgT.stream = 0;
    cfgT.attrs = at;
    cfgT.numAttrs = 1;
    cudaLaunchKernelEx(&cfgT, transform_kernel, Wi, y);
}